// round 7
// baseline (speedup 1.0000x reference)
#include <cuda_runtime.h>
#include <cstdint>

// ---------------------------------------------------------------------------
// Problem constants
// ---------------------------------------------------------------------------
#define N0 8000
#define N1 4000
#define N2 2000
#define DIM 128
#define BCOLS 384

#define BT0_OFF 0
#define BT1_OFF ((size_t)BCOLS * N0)
#define BT2_OFF ((size_t)BCOLS * (N0 + N1))

#define T0_OFF 0
#define T1_OFF ((size_t)N0 * BCOLS)
#define T2_OFF ((size_t)(N0 + N1) * BCOLS)
#define TOTAL_ROWS (N0 + N1 + N2)

// Bt: per-level column-major B (B^T, [n][k]); T: row-major [m][384] (tf32)
// Wt: per (i,j) transposed weights [n][k], tf32-rounded
__device__ float g_Bt[(size_t)BCOLS * TOTAL_ROWS];
__device__ float g_T[(size_t)TOTAL_ROWS * BCOLS];
__device__ float g_Wt[9 * DIM * DIM];

// ---------------------------------------------------------------------------
// Helpers (sm_80-compatible PTX only; harness lowers via compute_103)
// ---------------------------------------------------------------------------
__device__ __forceinline__ uint32_t smem_u32(const void* p) {
    uint32_t a;
    asm("{ .reg .u64 t; cvta.to.shared.u64 t, %1; cvt.u32.u64 %0, t; }"
        : "=r"(a) : "l"(p));
    return a;
}

__device__ __forceinline__ float to_tf32(float x) {
    uint32_t u;
    asm("cvt.rna.tf32.f32 %0, %1;" : "=r"(u) : "f"(x));
    return __uint_as_float(u);
}

#define CP_ASYNC_CG(dst, src, sz) \
    asm volatile("cp.async.cg.shared.global [%0], [%1], 16, %2;" \
        :: "r"(dst), "l"(src), "r"(sz) : "memory")
#define CP_ASYNC_CG16(dst, src) \
    asm volatile("cp.async.cg.shared.global [%0], [%1], 16;" \
        :: "r"(dst), "l"(src) : "memory")
#define CP_COMMIT() asm volatile("cp.async.commit_group;" ::: "memory")
#define CP_WAIT(n)  asm volatile("cp.async.wait_group " #n ";" ::: "memory")

#define LDSM_X4(r0, r1, r2, r3, addr) \
    asm volatile("ldmatrix.sync.aligned.m8n8.x4.shared.b16 {%0,%1,%2,%3}, [%4];" \
        : "=r"(r0), "=r"(r1), "=r"(r2), "=r"(r3) : "r"(addr))

#define MMA_TF32(c, a, b) \
    asm volatile("mma.sync.aligned.m16n8k8.row.col.f32.tf32.tf32.f32 " \
        "{%0,%1,%2,%3}, {%4,%5,%6,%7}, {%8,%9}, {%0,%1,%2,%3};" \
        : "+f"((c)[0]), "+f"((c)[1]), "+f"((c)[2]), "+f"((c)[3]) \
        : "r"((a)[0]), "r"((a)[1]), "r"((a)[2]), "r"((a)[3]), \
          "r"((b)[0]), "r"((b)[1]))

// BK32 tiles: rows are 128B (32 floats = 8 chunks of 16B); chunk ^ (row&7)
// keeps both cp.async writes and ldmatrix 8-row phases conflict-free.
__device__ __forceinline__ uint32_t tile_off32(int row, int chunk) {
    return (uint32_t)(row * 128 + ((chunk ^ (row & 7)) << 4));
}
// BK16 tiles (stagec): rows 64B = 4 chunks; chunk ^ ((row>>1)&3)
__device__ __forceinline__ uint32_t tile_off16(int row, int chunk) {
    return (uint32_t)(row * 64 + ((chunk ^ ((row >> 1) & 3)) << 4));
}

// ---------------------------------------------------------------------------
// buildA: dense/gather parts of B^T via 32x32 smem transpose, tf32-rounded.
// ---------------------------------------------------------------------------
__global__ void buildA_kernel(const float* __restrict__ h0,
                              const float* __restrict__ h1,
                              const float* __restrict__ h2,
                              const int* __restrict__ idx0,
                              const int* __restrict__ idx1) {
    int b = blockIdx.x;
    int nt = b % 12;
    int rb = b / 12;
    int level, r0, M;
    size_t bt_off;
    if (rb < 250)      { level = 0; r0 = rb * 32;         M = N0; bt_off = BT0_OFF; }
    else if (rb < 375) { level = 1; r0 = (rb - 250) * 32; M = N1; bt_off = BT1_OFF; }
    else               { level = 2; r0 = (rb - 375) * 32; M = N2; bt_off = BT2_OFF; }
    int n0 = nt * 32;

    __shared__ float tile[32][33];
    int tx = threadIdx.x & 31;
    int ty = threadIdx.x >> 5;

    for (int rr = ty; rr < 32; rr += 8) {
        int r = r0 + rr;
        int n = n0 + tx;
        float v = 0.0f;
        if (r < M) {
            if (level == 0) {
                if (n < DIM) v = h0[r * DIM + n];
            } else if (level == 1) {
                if (n < DIM)          v = h0[idx0[r] * DIM + n];
                else if (n < 2 * DIM) v = h1[r * DIM + (n - DIM)];
            } else {
                if (n < DIM)          v = h0[idx0[idx1[r]] * DIM + n];
                else if (n < 2 * DIM) v = h1[idx1[r] * DIM + (n - DIM)];
                else                  v = h2[r * DIM + (n - 2 * DIM)];
            }
        }
        tile[rr][tx] = to_tf32(v);
    }
    __syncthreads();

    float* dst = g_Bt + bt_off;
    for (int nn = ty; nn < 32; nn += 8) {
        int r = r0 + tx;
        if (r < M) dst[(size_t)(n0 + nn) * M + r] = tile[tx][nn];
    }
}

// ---------------------------------------------------------------------------
// buildB: scatters (unique indices -> plain stores, transposed target)
// ---------------------------------------------------------------------------
__global__ void buildB_kernel(const float* __restrict__ h1,
                              const float* __restrict__ h2,
                              const int* __restrict__ idx0,
                              const int* __restrict__ idx1) {
    int i = blockIdx.x * blockDim.x + threadIdx.x;
    if (i < N1 * DIM) {
        int s = i >> 7, c = i & 127;
        g_Bt[BT0_OFF + (size_t)(DIM + c) * N0 + idx0[s]] = to_tf32(h1[i]);
        return;
    }
    i -= N1 * DIM;
    if (i < N2 * DIM) {
        int s = i >> 7, c = i & 127;
        g_Bt[BT0_OFF + (size_t)(2 * DIM + c) * N0 + idx0[idx1[s]]] = to_tf32(h2[i]);
        return;
    }
    i -= N2 * DIM;
    if (i < N2 * DIM) {
        int s = i >> 7, c = i & 127;
        g_Bt[BT1_OFF + (size_t)(2 * DIM + c) * N1 + idx1[s]] = to_tf32(h2[i]);
    }
}

// ---------------------------------------------------------------------------
// buildW: Wt[ij][n][k] = rna(Ws[ij][k][n])
// ---------------------------------------------------------------------------
__global__ void buildW_kernel(const float* __restrict__ Ws) {
    int b = blockIdx.x;            // 144 blocks
    int ij = b / 16;
    int t  = b % 16;
    int tr = (t >> 2) * 32;
    int tc = (t & 3) * 32;
    __shared__ float tile[32][33];
    int tx = threadIdx.x & 31;
    int ty = threadIdx.x >> 5;
    const float* W = Ws + (size_t)ij * DIM * DIM;
    float* Wt = g_Wt + (size_t)ij * DIM * DIM;
    for (int rr = ty; rr < 32; rr += 8)
        tile[rr][tx] = to_tf32(W[(tr + rr) * DIM + tc + tx]);
    __syncthreads();
    for (int rr = ty; rr < 32; rr += 8)
        Wt[(tc + rr) * DIM + tr + tx] = tile[tx][rr];
}

// ---------------------------------------------------------------------------
// tc_gemm: T_i = adj_i @ B_i, mma.sync tf32 m16n8k8.
// CTA tile 128x128, warp tile 64x32 (8 warps: 2m x 4n), BK=32, THREE-stage
// cp.async pipeline (96KB/CTA, 2 CTAs/SM), ONE barrier per iter with
// RACE-FREE ordering:
//   CP_WAIT(1)      -> group it complete (group it+1 pending)
//   __syncthreads() -> all warps finished reading stage (it-1)%3
//   load_tile(it+2) -> writes stage (it+2)%3 == (it-1)%3  (now safe)
//   compute stage it%3
// Grid: (63+32+16)*3 = 333 CTAs; short level-2 CTAs last.
// ---------------------------------------------------------------------------
#define GEMM_CTAS 333
#define GEMM_STAGE 32768          // A 16KB + B 16KB
#define GEMM_SMEM (3 * GEMM_STAGE)

__global__ void __launch_bounds__(256, 2) tc_gemm_kernel(
    const float* __restrict__ adj0,
    const float* __restrict__ adj1,
    const float* __restrict__ adj2) {

    extern __shared__ char smem[];
    const uint32_t sbase = smem_u32(smem);

    const int tid  = threadIdx.x;
    const int lane = tid & 31;
    const int wid  = tid >> 5;
    const int warp_m = wid & 1;   // 0..1 (64 rows)
    const int warp_n = wid >> 1;  // 0..3 (32 cols)

    int b = blockIdx.x;
    const float* A;
    const float* Bt;
    float* Tp;
    int M, mt_, nt_;
    if (b < 189)      { A = adj0; Bt = g_Bt + BT0_OFF; Tp = g_T + T0_OFF; M = N0; mt_ = b / 3;         nt_ = b % 3; }
    else if (b < 285) { A = adj1; Bt = g_Bt + BT1_OFF; Tp = g_T + T1_OFF; M = N1; mt_ = (b - 189) / 3; nt_ = (b - 189) % 3; }
    else              { A = adj2; Bt = g_Bt + BT2_OFF; Tp = g_T + T2_OFF; M = N2; mt_ = (b - 285) / 3; nt_ = (b - 285) % 3; }
    const int K  = M;
    const int m0 = mt_ * 128;
    const int n0 = nt_ * 128;
    const int nk = (K + 31) / 32;

    // ldmatrix per-thread address components
    const int rlA   = lane & 15;
    const int acoff = lane >> 4;                       // 0/1
    uint32_t aoff[4]; int aswz[4];
#pragma unroll
    for (int mt = 0; mt < 4; mt++) {
        int row = warp_m * 64 + mt * 16 + rlA;
        aoff[mt] = (uint32_t)(row * 128);
        aswz[mt] = row & 7;
    }
    const int rlB   = (lane & 7) | ((lane & 16) >> 1); // 0..15
    const int bcoff = (lane >> 3) & 1;
    uint32_t boff[2]; int bswz[2];
#pragma unroll
    for (int p = 0; p < 2; p++) {
        int row = warp_n * 32 + p * 16 + rlB;
        boff[p] = (uint32_t)(row * 128);
        bswz[p] = row & 7;
    }

    float acc[4][4][4];
#pragma unroll
    for (int mt = 0; mt < 4; mt++)
#pragma unroll
        for (int nt = 0; nt < 4; nt++)
#pragma unroll
            for (int i = 0; i < 4; i++) acc[mt][nt][i] = 0.0f;

    // loader: A 4 chunks/thread, B 4 chunks/thread per BK32 stage.
    // Always commits (empty group when it >= nk keeps wait counts uniform).
    auto load_tile = [&](int it) {
        if (it >= nk) { CP_COMMIT(); return; }
        const int k0 = it * 32;
        const uint32_t ab = sbase + (uint32_t)(it % 3) * GEMM_STAGE;
        const uint32_t bb = ab + 16384;
#pragma unroll
        for (int i = 0; i < 4; i++) {
            int idx = i * 256 + tid;
            int m = idx >> 3, c = idx & 7;
            int gm = m0 + m;
            int kc = k0 + c * 4;
            bool ok = (gm < M) && (kc < K);
            const float* src = A + (size_t)(gm < M ? gm : 0) * K + (kc < K ? kc : 0);
            CP_ASYNC_CG(ab + tile_off32(m, c), src, ok ? 16u : 0u);
        }
#pragma unroll
        for (int i = 0; i < 4; i++) {
            int idx = i * 256 + tid;
            int n = idx >> 3, c = idx & 7;
            int kc = k0 + c * 4;
            bool ok = (kc < K);  // n0+n always < 384
            const float* src = Bt + (size_t)(n0 + n) * K + (kc < K ? kc : 0);
            CP_ASYNC_CG(bb + tile_off32(n, c), src, ok ? 16u : 0u);
        }
        CP_COMMIT();
    };

    load_tile(0);
    load_tile(1);

    for (int it = 0; it < nk; ++it) {
        CP_WAIT(1);          // group it done; group it+1 still pending
        __syncthreads();     // all warps done reading stage (it-1)%3
        load_tile(it + 2);   // safely recycle stage (it-1)%3

        const uint32_t ab = sbase + (uint32_t)(it % 3) * GEMM_STAGE;
        const uint32_t bb = ab + 16384;
#pragma unroll
        for (int kh = 0; kh < 4; kh++) {
            uint32_t afr[4][4], bfr[4][2];
            const int cA = kh * 2 + acoff;
            const int cB = kh * 2 + bcoff;
#pragma unroll
            for (int mt = 0; mt < 4; mt++) {
                uint32_t addr = ab + aoff[mt] + (uint32_t)((cA ^ aswz[mt]) << 4);
                LDSM_X4(afr[mt][0], afr[mt][1], afr[mt][2], afr[mt][3], addr);
            }
#pragma unroll
            for (int p = 0; p < 2; p++) {
                uint32_t addr = bb + boff[p] + (uint32_t)((cB ^ bswz[p]) << 4);
                LDSM_X4(bfr[2 * p][0], bfr[2 * p][1],
                        bfr[2 * p + 1][0], bfr[2 * p + 1][1], addr);
            }
#pragma unroll
            for (int mt = 0; mt < 4; mt++)
#pragma unroll
                for (int nt = 0; nt < 4; nt++)
                    MMA_TF32(acc[mt][nt], afr[mt], bfr[nt]);
        }
    }

    // Epilogue: rna-round to tf32 and store T (stagec consumes without cvt)
#pragma unroll
    for (int mt = 0; mt < 4; mt++) {
        int mr = m0 + warp_m * 64 + mt * 16 + (lane >> 2);
#pragma unroll
        for (int nt = 0; nt < 4; nt++) {
            int ng = n0 + warp_n * 32 + nt * 8 + ((lane & 3) << 1);
            if (mr < M) {
                float2 v = make_float2(to_tf32(acc[mt][nt][0]), to_tf32(acc[mt][nt][1]));
                *(float2*)(Tp + (size_t)mr * BCOLS + ng) = v;
            }
            if (mr + 8 < M) {
                float2 v = make_float2(to_tf32(acc[mt][nt][2]), to_tf32(acc[mt][nt][3]));
                *(float2*)(Tp + (size_t)(mr + 8) * BCOLS + ng) = v;
            }
        }
    }
}

// ---------------------------------------------------------------------------
// stagec_mma: out_i = sum_j relu(T_i[:, j*128:] @ W[i,j] + b[i,j]).
// CTA tile 64x128, warp tile 32x32 (8 warps: 2m x 4n), BK16, 3-stage.
// (Keeps two barriers per iter; the trailing one makes its early-issue
//  load pattern safe. ~20us total, not the critical path.)
// Grid: 125 + 63 + 32 = 220 CTAs.
// ---------------------------------------------------------------------------
#define STAGEC_CTAS 220

__global__ void __launch_bounds__(256) stagec_mma_kernel(
    const float* __restrict__ bs,
    float* __restrict__ out) {

    __shared__ __align__(16) float sT[3][1024];   // 12 KB (64 rows x 16)
    __shared__ __align__(16) float sW[3][2048];   // 24 KB (128 rows x 16)

    int b = blockIdx.x;
    int level, m0, M;
    const float* Tp;
    size_t outoff;
    if (b < 125)      { level = 0; m0 = b * 64;         M = N0; Tp = g_T + T0_OFF; outoff = 0; }
    else if (b < 188) { level = 1; m0 = (b - 125) * 64; M = N1; Tp = g_T + T1_OFF; outoff = (size_t)N0 * DIM; }
    else              { level = 2; m0 = (b - 188) * 64; M = N2; Tp = g_T + T2_OFF; outoff = (size_t)(N0 + N1) * DIM; }

    const int tid  = threadIdx.x;
    const int lane = tid & 31;
    const int wid  = tid >> 5;
    const int warp_m = wid & 1;    // 32 rows each
    const int warp_n = wid >> 1;   // 32 cols each
    const uint32_t tB = smem_u32(sT[0]);
    const uint32_t wB = smem_u32(sW[0]);

    const int rlA   = lane & 15;
    const int acoff = lane >> 4;
    uint32_t aoff[2]; int aswz[2];
#pragma unroll
    for (int mt = 0; mt < 2; mt++) {
        int row = warp_m * 32 + mt * 16 + rlA;
        aoff[mt] = (uint32_t)(row * 64);
        aswz[mt] = (row >> 1) & 3;
    }
    const int rlB   = (lane & 7) | ((lane & 16) >> 1);
    const int bcoff = (lane >> 3) & 1;
    uint32_t boff[2]; int bswz[2];
#pragma unroll
    for (int p = 0; p < 2; p++) {
        int row = warp_n * 32 + p * 16 + rlB;
        boff[p] = (uint32_t)(row * 64);
        bswz[p] = (row >> 1) & 3;
    }

    auto load_tile = [&](int it) {
        if (it >= 24) { CP_COMMIT(); return; }
        const int st = it % 3;
        const int j  = it >> 3;
        const int kl = (it & 7) * 16;
        const float* Wsrc = g_Wt + (size_t)(level * 3 + j) * DIM * DIM;
        {   // T: 64 rows x 4 chunks = 256 -> 1 chunk/thread
            int m = tid >> 2, c = tid & 3;
            int gm = m0 + m;
            uint32_t sz = (gm < M) ? 16u : 0u;
            const float* src = Tp + (size_t)(gm < M ? gm : 0) * BCOLS + it * 16 + c * 4;
            CP_ASYNC_CG(tB + st * 4096 + tile_off16(m, c), src, sz);
        }
#pragma unroll
        for (int i = 0; i < 2; i++) {   // W: 128 rows x 4 chunks = 512 -> 2/thread
            int idx = i * 256 + tid;
            int n = idx >> 2, c = idx & 3;
            CP_ASYNC_CG16(wB + st * 8192 + tile_off16(n, c),
                          Wsrc + (size_t)n * DIM + kl + c * 4);
        }
        CP_COMMIT();
    };

    float acc[2][4][4], res[2][4][4];
#pragma unroll
    for (int mt = 0; mt < 2; mt++)
#pragma unroll
        for (int nt = 0; nt < 4; nt++)
#pragma unroll
            for (int i = 0; i < 4; i++) { acc[mt][nt][i] = 0.0f; res[mt][nt][i] = 0.0f; }

    load_tile(0);
    load_tile(1);

    for (int it = 0; it < 24; ++it) {
        load_tile(it + 2);
        CP_WAIT(2);
        __syncthreads();

        const int st = it % 3;
        const uint32_t tb = tB + st * 4096;
        const uint32_t wb = wB + st * 8192;
#pragma unroll
        for (int kh = 0; kh < 2; kh++) {
            uint32_t afr[2][4], bfr[4][2];
#pragma unroll
            for (int mt = 0; mt < 2; mt++) {
                uint32_t addr = tb + aoff[mt]
                    + (uint32_t)((((kh << 1) + acoff) ^ aswz[mt]) << 4);
                LDSM_X4(afr[mt][0], afr[mt][1], afr[mt][2], afr[mt][3], addr);
            }
#pragma unroll
            for (int p = 0; p < 2; p++) {
                uint32_t addr = wb + boff[p]
                    + (uint32_t)((((kh << 1) + bcoff) ^ bswz[p]) << 4);
                LDSM_X4(bfr[2 * p][0], bfr[2 * p][1],
                        bfr[2 * p + 1][0], bfr[2 * p + 1][1], addr);
            }
#pragma unroll
            for (int mt = 0; mt < 2; mt++)
#pragma unroll
                for (int nt = 0; nt < 4; nt++)
                    MMA_TF32(acc[mt][nt], afr[mt], bfr[nt]);
        }

        if ((it & 7) == 7) {         // end of segment j: relu + accumulate
            const int j = it >> 3;
            const float* bsj = bs + (size_t)(level * 3 + j) * DIM;
#pragma unroll
            for (int nt = 0; nt < 4; nt++) {
                int col = warp_n * 32 + nt * 8 + ((lane & 3) << 1);
                float bx = bsj[col], by = bsj[col + 1];
#pragma unroll
                for (int mt = 0; mt < 2; mt++) {
                    res[mt][nt][0] += fmaxf(acc[mt][nt][0] + bx, 0.0f);
                    res[mt][nt][1] += fmaxf(acc[mt][nt][1] + by, 0.0f);
                    res[mt][nt][2] += fmaxf(acc[mt][nt][2] + bx, 0.0f);
                    res[mt][nt][3] += fmaxf(acc[mt][nt][3] + by, 0.0f);
                    acc[mt][nt][0] = 0.0f; acc[mt][nt][1] = 0.0f;
                    acc[mt][nt][2] = 0.0f; acc[mt][nt][3] = 0.0f;
                }
            }
        }
        __syncthreads();
    }

#pragma unroll
    for (int mt = 0; mt < 2; mt++) {
        int mr = m0 + warp_m * 32 + mt * 16 + (lane >> 2);
#pragma unroll
        for (int nt = 0; nt < 4; nt++) {
            int col = warp_n * 32 + nt * 8 + ((lane & 3) << 1);
            if (mr < M) {
                float2 v = make_float2(res[mt][nt][0], res[mt][nt][1]);
                *(float2*)(out + outoff + (size_t)mr * DIM + col) = v;
            }
            if (mr + 8 < M) {
                float2 v = make_float2(res[mt][nt][2], res[mt][nt][3]);
                *(float2*)(out + outoff + (size_t)(mr + 8) * DIM + col) = v;
            }
        }
    }
}

// ---------------------------------------------------------------------------
// kernel_launch
// Inputs: adj0, adj1, adj2, h0, h1, h2, idx0, idx1, Ws, bs
// ---------------------------------------------------------------------------
extern "C" void kernel_launch(void* const* d_in, const int* in_sizes, int n_in,
                              void* d_out, int out_size) {
    const float* adj0 = (const float*)d_in[0];
    const float* adj1 = (const float*)d_in[1];
    const float* adj2 = (const float*)d_in[2];
    const float* h0   = (const float*)d_in[3];
    const float* h1   = (const float*)d_in[4];
    const float* h2   = (const float*)d_in[5];
    const int*   idx0 = (const int*)d_in[6];
    const int*   idx1 = (const int*)d_in[7];
    const float* Ws   = (const float*)d_in[8];
    const float* bs   = (const float*)d_in[9];
    float* out = (float*)d_out;

    static bool attr_set = false;
    if (!attr_set) {
        cudaFuncSetAttribute(tc_gemm_kernel,
                             cudaFuncAttributeMaxDynamicSharedMemorySize, GEMM_SMEM);
        attr_set = true;
    }

    buildA_kernel<<<438 * 12, 256>>>(h0, h1, h2, idx0, idx1);
    {
        int total = (N1 + N2 + N2) * DIM;
        buildB_kernel<<<(total + 255) / 256, 256>>>(h1, h2, idx0, idx1);
    }
    buildW_kernel<<<144, 256>>>(Ws);
    tc_gemm_kernel<<<GEMM_CTAS, 256, GEMM_SMEM>>>(adj0, adj1, adj2);
    stagec_mma_kernel<<<STAGEC_CTAS, 256>>>(bs, out);
}

// round 11
// speedup vs baseline: 1.3536x; 1.3536x over previous
#include <cuda_runtime.h>
#include <cuda_fp16.h>
#include <cstdint>

// ---------------------------------------------------------------------------
// Problem constants
// ---------------------------------------------------------------------------
#define N0 8000
#define N1 4000
#define N2 2000
#define DIM 128
#define BCOLS 384

#define BT0_OFF 0
#define BT1_OFF ((size_t)BCOLS * N0)
#define BT2_OFF ((size_t)BCOLS * (N0 + N1))

#define T0_OFF 0
#define T1_OFF ((size_t)N0 * BCOLS)
#define T2_OFF ((size_t)(N0 + N1) * BCOLS)
#define TOTAL_ROWS (N0 + N1 + N2)

// Bth: per-level B^T [n][k] fp16 (10.8 MB); T: [m][384] fp32, tf32-rounded
// (21.5 MB); Wt: transposed weights, tf32-rounded (0.6 MB).
// Total static ~33 MB — BELOW the proven-passing R5 footprint (no 168MB
// adj copy: fp32 adj is converted to fp16 inside the GEMM kernel).
__device__ __half g_Bth[(size_t)BCOLS * TOTAL_ROWS];
__device__ float  g_T[(size_t)TOTAL_ROWS * BCOLS];
__device__ float  g_Wt[9 * DIM * DIM];

// ---------------------------------------------------------------------------
// Helpers (sm_80-compatible PTX only; harness lowers via compute_103)
// ---------------------------------------------------------------------------
__device__ __forceinline__ uint32_t smem_u32(const void* p) {
    uint32_t a;
    asm("{ .reg .u64 t; cvta.to.shared.u64 t, %1; cvt.u32.u64 %0, t; }"
        : "=r"(a) : "l"(p));
    return a;
}

__device__ __forceinline__ float to_tf32(float x) {
    uint32_t u;
    asm("cvt.rna.tf32.f32 %0, %1;" : "=r"(u) : "f"(x));
    return __uint_as_float(u);
}

#define CP_ASYNC_CG(dst, src, sz) \
    asm volatile("cp.async.cg.shared.global [%0], [%1], 16, %2;" \
        :: "r"(dst), "l"(src), "r"(sz) : "memory")
#define CP_ASYNC_CG16(dst, src) \
    asm volatile("cp.async.cg.shared.global [%0], [%1], 16;" \
        :: "r"(dst), "l"(src) : "memory")
#define CP_COMMIT() asm volatile("cp.async.commit_group;" ::: "memory")
#define CP_WAIT(n)  asm volatile("cp.async.wait_group " #n ";" ::: "memory")

#define LDSM_X4(r0, r1, r2, r3, addr) \
    asm volatile("ldmatrix.sync.aligned.m8n8.x4.shared.b16 {%0,%1,%2,%3}, [%4];" \
        : "=r"(r0), "=r"(r1), "=r"(r2), "=r"(r3) : "r"(addr))

// fp16 MMA, f32 accumulate: m16n8k16
#define MMA_F16(c, a, b) \
    asm volatile("mma.sync.aligned.m16n8k16.row.col.f32.f16.f16.f32 " \
        "{%0,%1,%2,%3}, {%4,%5,%6,%7}, {%8,%9}, {%0,%1,%2,%3};" \
        : "+f"((c)[0]), "+f"((c)[1]), "+f"((c)[2]), "+f"((c)[3]) \
        : "r"((a)[0]), "r"((a)[1]), "r"((a)[2]), "r"((a)[3]), \
          "r"((b)[0]), "r"((b)[1]))

// tf32 MMA (stagec): m16n8k8
#define MMA_TF32(c, a, b) \
    asm volatile("mma.sync.aligned.m16n8k8.row.col.f32.tf32.tf32.f32 " \
        "{%0,%1,%2,%3}, {%4,%5,%6,%7}, {%8,%9}, {%0,%1,%2,%3};" \
        : "+f"((c)[0]), "+f"((c)[1]), "+f"((c)[2]), "+f"((c)[3]) \
        : "r"((a)[0]), "r"((a)[1]), "r"((a)[2]), "r"((a)[3]), \
          "r"((b)[0]), "r"((b)[1]))

// 128B-row b16 tiles (fp16 BK64): 8 chunks of 16B; chunk ^ (row&7)
__device__ __forceinline__ uint32_t tile_off128(int row, int chunk) {
    return (uint32_t)(row * 128 + ((chunk ^ (row & 7)) << 4));
}
// 64B-row tiles (stagec fp32 BK16): 4 chunks; chunk ^ ((row>>1)&3)
__device__ __forceinline__ uint32_t tile_off16(int row, int chunk) {
    return (uint32_t)(row * 64 + ((chunk ^ ((row >> 1) & 3)) << 4));
}

// ---------------------------------------------------------------------------
// buildA: dense/gather parts of B^T via 32x32 smem transpose, fp16-rna.
// ---------------------------------------------------------------------------
__global__ void buildA_kernel(const float* __restrict__ h0,
                              const float* __restrict__ h1,
                              const float* __restrict__ h2,
                              const int* __restrict__ idx0,
                              const int* __restrict__ idx1) {
    int b = blockIdx.x;
    int nt = b % 12;
    int rb = b / 12;
    int level, r0, M;
    size_t bt_off;
    if (rb < 250)      { level = 0; r0 = rb * 32;         M = N0; bt_off = BT0_OFF; }
    else if (rb < 375) { level = 1; r0 = (rb - 250) * 32; M = N1; bt_off = BT1_OFF; }
    else               { level = 2; r0 = (rb - 375) * 32; M = N2; bt_off = BT2_OFF; }
    int n0 = nt * 32;

    __shared__ float tile[32][33];
    int tx = threadIdx.x & 31;
    int ty = threadIdx.x >> 5;

    for (int rr = ty; rr < 32; rr += 8) {
        int r = r0 + rr;
        int n = n0 + tx;
        float v = 0.0f;
        if (r < M) {
            if (level == 0) {
                if (n < DIM) v = h0[r * DIM + n];
            } else if (level == 1) {
                if (n < DIM)          v = h0[idx0[r] * DIM + n];
                else if (n < 2 * DIM) v = h1[r * DIM + (n - DIM)];
            } else {
                if (n < DIM)          v = h0[idx0[idx1[r]] * DIM + n];
                else if (n < 2 * DIM) v = h1[idx1[r] * DIM + (n - DIM)];
                else                  v = h2[r * DIM + (n - 2 * DIM)];
            }
        }
        tile[rr][tx] = v;
    }
    __syncthreads();

    __half* dst = g_Bth + bt_off;
    for (int nn = ty; nn < 32; nn += 8) {
        int r = r0 + tx;
        if (r < M) dst[(size_t)(n0 + nn) * M + r] = __float2half_rn(tile[tx][nn]);
    }
}

// ---------------------------------------------------------------------------
// buildB: scatters (unique indices -> plain stores, transposed fp16 target)
// ---------------------------------------------------------------------------
__global__ void buildB_kernel(const float* __restrict__ h1,
                              const float* __restrict__ h2,
                              const int* __restrict__ idx0,
                              const int* __restrict__ idx1) {
    int i = blockIdx.x * blockDim.x + threadIdx.x;
    if (i < N1 * DIM) {
        int s = i >> 7, c = i & 127;
        g_Bth[BT0_OFF + (size_t)(DIM + c) * N0 + idx0[s]] = __float2half_rn(h1[i]);
        return;
    }
    i -= N1 * DIM;
    if (i < N2 * DIM) {
        int s = i >> 7, c = i & 127;
        g_Bth[BT0_OFF + (size_t)(2 * DIM + c) * N0 + idx0[idx1[s]]] = __float2half_rn(h2[i]);
        return;
    }
    i -= N2 * DIM;
    if (i < N2 * DIM) {
        int s = i >> 7, c = i & 127;
        g_Bth[BT1_OFF + (size_t)(2 * DIM + c) * N1 + idx1[s]] = __float2half_rn(h2[i]);
    }
}

// ---------------------------------------------------------------------------
// buildW: Wt[ij][n][k] = rna_tf32(Ws[ij][k][n])  (stagec stays tf32)
// ---------------------------------------------------------------------------
__global__ void buildW_kernel(const float* __restrict__ Ws) {
    int b = blockIdx.x;            // 144 blocks
    int ij = b / 16;
    int t  = b % 16;
    int tr = (t >> 2) * 32;
    int tc = (t & 3) * 32;
    __shared__ float tile[32][33];
    int tx = threadIdx.x & 31;
    int ty = threadIdx.x >> 5;
    const float* W = Ws + (size_t)ij * DIM * DIM;
    float* Wt = g_Wt + (size_t)ij * DIM * DIM;
    for (int rr = ty; rr < 32; rr += 8)
        tile[rr][tx] = to_tf32(W[(tr + rr) * DIM + tc + tx]);
    __syncthreads();
    for (int rr = ty; rr < 32; rr += 8)
        Wt[(tc + rr) * DIM + tr + tx] = tile[tx][rr];
}

// ---------------------------------------------------------------------------
// tc_gemm: T_i = adj_i @ B_i, fp16 mma.sync m16n8k16, f32 accum.
// A stays fp32 in HBM; each CTA converts its A tile to fp16 in smem.
// CTA tile 128x128, warp tile 64x32 (8 warps: 2m x 4n), BK=64.
// smem (112KB/CTA, 2 CTA/SM):
//   Af32 double-buffered 2x32KB (linear 256B rows, cp.async target)
//   Ah   single 16KB (swizzled fp16, conversion target, ldmatrix source)
//   Bh   double-buffered 2x16KB (swizzled fp16, cp.async target)
// Per-iter: [load it+1 / commit] -> wait -> sync -> convert -> sync ->
//           compute -> sync.  All buffer recycles barrier-protected.
// Grid: (63+32+16)*3 = 333 CTAs.
// ---------------------------------------------------------------------------
#define GEMM_CTAS 333
#define AF32_SZ  32768
#define AH_OFF   65536
#define BH_OFF   81920
#define BH_SZ    16384
#define GEMM_SMEM 114688   // 112 KB

__global__ void __launch_bounds__(256, 2) tc_gemm_kernel(
    const float* __restrict__ adj0,
    const float* __restrict__ adj1,
    const float* __restrict__ adj2) {

    extern __shared__ char smem[];
    const uint32_t sbase = smem_u32(smem);

    const int tid  = threadIdx.x;
    const int lane = tid & 31;
    const int wid  = tid >> 5;
    const int warp_m = wid & 1;   // 0..1 (64 rows)
    const int warp_n = wid >> 1;  // 0..3 (32 cols)

    int b = blockIdx.x;
    const float* A;
    const __half* Bt;
    float* Tp;
    int M, mt_, nt_;
    if (b < 189)      { A = adj0; Bt = g_Bth + BT0_OFF; Tp = g_T + T0_OFF; M = N0; mt_ = b / 3;         nt_ = b % 3; }
    else if (b < 285) { A = adj1; Bt = g_Bth + BT1_OFF; Tp = g_T + T1_OFF; M = N1; mt_ = (b - 189) / 3; nt_ = (b - 189) % 3; }
    else              { A = adj2; Bt = g_Bth + BT2_OFF; Tp = g_T + T2_OFF; M = N2; mt_ = (b - 285) / 3; nt_ = (b - 285) % 3; }
    const int K  = M;
    const int m0 = mt_ * 128;
    const int n0 = nt_ * 128;
    const int nk = (K + 63) / 64;

    // ldmatrix per-thread address components (same mapping as proven R5/R8)
    const int rlA   = lane & 15;
    const int acoff = lane >> 4;                       // 0/1
    uint32_t aoff[4]; int aswz[4];
#pragma unroll
    for (int mt = 0; mt < 4; mt++) {
        int row = warp_m * 64 + mt * 16 + rlA;
        aoff[mt] = (uint32_t)(row * 128);
        aswz[mt] = row & 7;
    }
    const int rlB   = (lane & 7) | ((lane & 16) >> 1); // 0..15
    const int bcoff = (lane >> 3) & 1;
    uint32_t boff[2]; int bswz[2];
#pragma unroll
    for (int p = 0; p < 2; p++) {
        int row = warp_n * 32 + p * 16 + rlB;
        boff[p] = (uint32_t)(row * 128);
        bswz[p] = row & 7;
    }

    float acc[4][4][4];
#pragma unroll
    for (int mt = 0; mt < 4; mt++)
#pragma unroll
        for (int nt = 0; nt < 4; nt++)
#pragma unroll
            for (int i = 0; i < 4; i++) acc[mt][nt][i] = 0.0f;

    // loader: A fp32 8 chunks/thread (linear), B fp16 4 chunks/thread (swz)
    auto load_tile = [&](int it) {
        const int k0 = it * 64;
        const uint32_t af = sbase + (uint32_t)(it & 1) * AF32_SZ;
        const uint32_t bh = sbase + BH_OFF + (uint32_t)(it & 1) * BH_SZ;
#pragma unroll
        for (int i = 0; i < 8; i++) {
            int idx = i * 256 + tid;
            int m = idx >> 4, c = idx & 15;     // 16 chunks of 16B per 256B row
            int gm = m0 + m;
            int kc = k0 + c * 4;
            bool ok = (gm < M) && (kc < K);     // zero-fill via src-size 0
            const float* src = A + (size_t)(gm < M ? gm : 0) * K + (kc < K ? kc : 0);
            CP_ASYNC_CG(af + (uint32_t)(m * 256 + c * 16), src, ok ? 16u : 0u);
        }
#pragma unroll
        for (int i = 0; i < 4; i++) {
            int idx = i * 256 + tid;
            int n = idx >> 3, c = idx & 7;      // 8 chunks of 16B per 128B row
            int kc = k0 + c * 8;
            bool ok = (kc < K);                 // n0+n always < 384
            const __half* src = Bt + (size_t)(n0 + n) * K + (kc < K ? kc : 0);
            CP_ASYNC_CG(bh + tile_off128(n, c), src, ok ? 16u : 0u);
        }
    };

    load_tile(0);
    CP_COMMIT();

    for (int it = 0; it < nk; ++it) {
        bool more = (it + 1 < nk);
        if (more) { load_tile(it + 1); CP_COMMIT(); }   // other buffers; safe
        if (more) { CP_WAIT(1); } else { CP_WAIT(0); }
        __syncthreads();   // stage (it&1) ready everywhere; Ah free (prev sync)

        // ---- convert Af32[it&1] -> Ah (fp16, swizzled) ----
        {
            const char* af = smem + (it & 1) * AF32_SZ;
#pragma unroll
            for (int i = 0; i < 4; i++) {
                int q = i * 256 + tid;          // Ah chunk id, 1024 total
                int row = q >> 3, cq = q & 7;
                const float4* s = (const float4*)(af + row * 256 + cq * 32);
                float4 v0 = s[0];
                float4 v1 = s[1];
                __half2 p0 = __floats2half2_rn(v0.x, v0.y);
                __half2 p1 = __floats2half2_rn(v0.z, v0.w);
                __half2 p2 = __floats2half2_rn(v1.x, v1.y);
                __half2 p3 = __floats2half2_rn(v1.z, v1.w);
                uint4 pk;
                pk.x = *(uint32_t*)&p0;
                pk.y = *(uint32_t*)&p1;
                pk.z = *(uint32_t*)&p2;
                pk.w = *(uint32_t*)&p3;
                *(uint4*)(smem + AH_OFF + tile_off128(row, cq)) = pk;
            }
        }
        __syncthreads();   // Ah ready for all warps

        // ---- compute: LDSM from Ah + Bh[it&1], MMA_F16 ----
        const uint32_t ah = sbase + AH_OFF;
        const uint32_t bh = sbase + BH_OFF + (uint32_t)(it & 1) * BH_SZ;
#pragma unroll
        for (int kh = 0; kh < 4; kh++) {       // each kh = k16
            uint32_t afr[4][4], bfr[4][2];
            const int cA = kh * 2 + acoff;
            const int cB = kh * 2 + bcoff;
#pragma unroll
            for (int mt = 0; mt < 4; mt++) {
                uint32_t addr = ah + aoff[mt] + (uint32_t)((cA ^ aswz[mt]) << 4);
                LDSM_X4(afr[mt][0], afr[mt][1], afr[mt][2], afr[mt][3], addr);
            }
#pragma unroll
            for (int p = 0; p < 2; p++) {
                uint32_t addr = bh + boff[p] + (uint32_t)((cB ^ bswz[p]) << 4);
                LDSM_X4(bfr[2 * p][0], bfr[2 * p][1],
                        bfr[2 * p + 1][0], bfr[2 * p + 1][1], addr);
            }
#pragma unroll
            for (int mt = 0; mt < 4; mt++)
#pragma unroll
                for (int nt = 0; nt < 4; nt++)
                    MMA_F16(acc[mt][nt], afr[mt], bfr[nt]);
        }
        __syncthreads();   // Bh[it&1] / Af32[it&1] free for next iter's load
    }

    // Epilogue: rna-round to tf32 and store T (stagec consumes without cvt)
#pragma unroll
    for (int mt = 0; mt < 4; mt++) {
        int mr = m0 + warp_m * 64 + mt * 16 + (lane >> 2);
#pragma unroll
        for (int nt = 0; nt < 4; nt++) {
            int ng = n0 + warp_n * 32 + nt * 8 + ((lane & 3) << 1);
            if (mr < M) {
                float2 v = make_float2(to_tf32(acc[mt][nt][0]), to_tf32(acc[mt][nt][1]));
                *(float2*)(Tp + (size_t)mr * BCOLS + ng) = v;
            }
            if (mr + 8 < M) {
                float2 v = make_float2(to_tf32(acc[mt][nt][2]), to_tf32(acc[mt][nt][3]));
                *(float2*)(Tp + (size_t)(mr + 8) * BCOLS + ng) = v;
            }
        }
    }
}

// ---------------------------------------------------------------------------
// stagec_mma: out_i = sum_j relu(T_i[:, j*128:] @ W[i,j] + b[i,j])  (tf32).
// CTA tile 64x128, warp tile 32x32 (8 warps: 2m x 4n), BK16, 3-stage.
// Grid: 125 + 63 + 32 = 220 CTAs.  (Unchanged from passing R5.)
// ---------------------------------------------------------------------------
#define STAGEC_CTAS 220

__global__ void __launch_bounds__(256) stagec_mma_kernel(
    const float* __restrict__ bs,
    float* __restrict__ out) {

    __shared__ __align__(16) float sT[3][1024];   // 12 KB (64 rows x 16)
    __shared__ __align__(16) float sW[3][2048];   // 24 KB (128 rows x 16)

    int b = blockIdx.x;
    int level, m0, M;
    const float* Tp;
    size_t outoff;
    if (b < 125)      { level = 0; m0 = b * 64;         M = N0; Tp = g_T + T0_OFF; outoff = 0; }
    else if (b < 188) { level = 1; m0 = (b - 125) * 64; M = N1; Tp = g_T + T1_OFF; outoff = (size_t)N0 * DIM; }
    else              { level = 2; m0 = (b - 188) * 64; M = N2; Tp = g_T + T2_OFF; outoff = (size_t)(N0 + N1) * DIM; }

    const int tid  = threadIdx.x;
    const int lane = tid & 31;
    const int wid  = tid >> 5;
    const int warp_m = wid & 1;    // 32 rows each
    const int warp_n = wid >> 1;   // 32 cols each
    const uint32_t tB = smem_u32(sT[0]);
    const uint32_t wB = smem_u32(sW[0]);

    const int rlA   = lane & 15;
    const int acoff = lane >> 4;
    uint32_t aoff[2]; int aswz[2];
#pragma unroll
    for (int mt = 0; mt < 2; mt++) {
        int row = warp_m * 32 + mt * 16 + rlA;
        aoff[mt] = (uint32_t)(row * 64);
        aswz[mt] = (row >> 1) & 3;
    }
    const int rlB   = (lane & 7) | ((lane & 16) >> 1);
    const int bcoff = (lane >> 3) & 1;
    uint32_t boff[2]; int bswz[2];
#pragma unroll
    for (int p = 0; p < 2; p++) {
        int row = warp_n * 32 + p * 16 + rlB;
        boff[p] = (uint32_t)(row * 64);
        bswz[p] = (row >> 1) & 3;
    }

    auto load_tile = [&](int it) {
        if (it >= 24) { CP_COMMIT(); return; }
        const int st = it % 3;
        const int j  = it >> 3;
        const int kl = (it & 7) * 16;
        const float* Wsrc = g_Wt + (size_t)(level * 3 + j) * DIM * DIM;
        {   // T: 64 rows x 4 chunks = 256 -> 1 chunk/thread
            int m = tid >> 2, c = tid & 3;
            int gm = m0 + m;
            uint32_t sz = (gm < M) ? 16u : 0u;
            const float* src = Tp + (size_t)(gm < M ? gm : 0) * BCOLS + it * 16 + c * 4;
            CP_ASYNC_CG(tB + st * 4096 + tile_off16(m, c), src, sz);
        }
#pragma unroll
        for (int i = 0; i < 2; i++) {   // W: 128 rows x 4 chunks = 512 -> 2/thread
            int idx = i * 256 + tid;
            int n = idx >> 2, c = idx & 3;
            CP_ASYNC_CG16(wB + st * 8192 + tile_off16(n, c),
                          Wsrc + (size_t)n * DIM + kl + c * 4);
        }
        CP_COMMIT();
    };

    float acc[2][4][4], res[2][4][4];
#pragma unroll
    for (int mt = 0; mt < 2; mt++)
#pragma unroll
        for (int nt = 0; nt < 4; nt++)
#pragma unroll
            for (int i = 0; i < 4; i++) { acc[mt][nt][i] = 0.0f; res[mt][nt][i] = 0.0f; }

    load_tile(0);
    load_tile(1);

    for (int it = 0; it < 24; ++it) {
        load_tile(it + 2);
        CP_WAIT(2);
        __syncthreads();

        const int st = it % 3;
        const uint32_t tb = tB + st * 4096;
        const uint32_t wb = wB + st * 8192;
#pragma unroll
        for (int kh = 0; kh < 2; kh++) {
            uint32_t afr[2][4], bfr[4][2];
#pragma unroll
            for (int mt = 0; mt < 2; mt++) {
                uint32_t addr = tb + aoff[mt]
                    + (uint32_t)((((kh << 1) + acoff) ^ aswz[mt]) << 4);
                LDSM_X4(afr[mt][0], afr[mt][1], afr[mt][2], afr[mt][3], addr);
            }
#pragma unroll
            for (int p = 0; p < 2; p++) {
                uint32_t addr = wb + boff[p]
                    + (uint32_t)((((kh << 1) + bcoff) ^ bswz[p]) << 4);
                LDSM_X4(bfr[2 * p][0], bfr[2 * p][1],
                        bfr[2 * p + 1][0], bfr[2 * p + 1][1], addr);
            }
#pragma unroll
            for (int mt = 0; mt < 2; mt++)
#pragma unroll
                for (int nt = 0; nt < 4; nt++)
                    MMA_TF32(acc[mt][nt], afr[mt], bfr[nt]);
        }

        if ((it & 7) == 7) {         // end of segment j: relu + accumulate
            const int j = it >> 3;
            const float* bsj = bs + (size_t)(level * 3 + j) * DIM;
#pragma unroll
            for (int nt = 0; nt < 4; nt++) {
                int col = warp_n * 32 + nt * 8 + ((lane & 3) << 1);
                float bx = bsj[col], by = bsj[col + 1];
#pragma unroll
                for (int mt = 0; mt < 2; mt++) {
                    res[mt][nt][0] += fmaxf(acc[mt][nt][0] + bx, 0.0f);
                    res[mt][nt][1] += fmaxf(acc[mt][nt][1] + by, 0.0f);
                    res[mt][nt][2] += fmaxf(acc[mt][nt][2] + bx, 0.0f);
                    res[mt][nt][3] += fmaxf(acc[mt][nt][3] + by, 0.0f);
                    acc[mt][nt][0] = 0.0f; acc[mt][nt][1] = 0.0f;
                    acc[mt][nt][2] = 0.0f; acc[mt][nt][3] = 0.0f;
                }
            }
        }
        __syncthreads();
    }

#pragma unroll
    for (int mt = 0; mt < 2; mt++) {
        int mr = m0 + warp_m * 32 + mt * 16 + (lane >> 2);
#pragma unroll
        for (int nt = 0; nt < 4; nt++) {
            int col = warp_n * 32 + nt * 8 + ((lane & 3) << 1);
            if (mr < M) {
                float2 v = make_float2(res[mt][nt][0], res[mt][nt][1]);
                *(float2*)(out + outoff + (size_t)mr * DIM + col) = v;
            }
            if (mr + 8 < M) {
                float2 v = make_float2(res[mt][nt][2], res[mt][nt][3]);
                *(float2*)(out + outoff + (size_t)(mr + 8) * DIM + col) = v;
            }
        }
    }
}

// ---------------------------------------------------------------------------
// kernel_launch  (identical structure to the 3x-passing R5/R7 version)
// Inputs: adj0, adj1, adj2, h0, h1, h2, idx0, idx1, Ws, bs
// ---------------------------------------------------------------------------
extern "C" void kernel_launch(void* const* d_in, const int* in_sizes, int n_in,
                              void* d_out, int out_size) {
    const float* adj0 = (const float*)d_in[0];
    const float* adj1 = (const float*)d_in[1];
    const float* adj2 = (const float*)d_in[2];
    const float* h0   = (const float*)d_in[3];
    const float* h1   = (const float*)d_in[4];
    const float* h2   = (const float*)d_in[5];
    const int*   idx0 = (const int*)d_in[6];
    const int*   idx1 = (const int*)d_in[7];
    const float* Ws   = (const float*)d_in[8];
    const float* bs   = (const float*)d_in[9];
    float* out = (float*)d_out;

    static bool attr_set = false;
    if (!attr_set) {
        cudaFuncSetAttribute(tc_gemm_kernel,
                             cudaFuncAttributeMaxDynamicSharedMemorySize, GEMM_SMEM);
        attr_set = true;
    }

    buildA_kernel<<<438 * 12, 256>>>(h0, h1, h2, idx0, idx1);
    {
        int total = (N1 + N2 + N2) * DIM;
        buildB_kernel<<<(total + 255) / 256, 256>>>(h1, h2, idx0, idx1);
    }
    buildW_kernel<<<144, 256>>>(Ws);
    tc_gemm_kernel<<<GEMM_CTAS, 256, GEMM_SMEM>>>(adj0, adj1, adj2);
    stagec_mma_kernel<<<STAGEC_CTAS, 256>>>(bs, out);
}